// round 8
// baseline (speedup 1.0000x reference)
#include <cuda_runtime.h>
#include <math.h>

#define WPB 8           // warps per block
#define NC  1000        // classes
#define NF4 250         // float4 per row
#define NK  10          // attack classes per row
#define L2E 1.4426950408889634f

__device__ __forceinline__ float ex2f(float x) {
    float r; asm("ex2.approx.f32 %0, %1;" : "=f"(r) : "f"(x)); return r;
}
__device__ __forceinline__ float lg2f(float x) {
    float r; asm("lg2.approx.f32 %0, %1;" : "=f"(r) : "f"(x)); return r;
}
__device__ __forceinline__ float pow9f(float x) {
    float x2 = x * x, x4 = x2 * x2, x8 = x4 * x4; return x8 * x;
}
__device__ __forceinline__ float pow10f(float x) {
    float x2 = x * x, x4 = x2 * x2, x8 = x4 * x4; return x8 * x2;
}
__device__ __forceinline__ float rootf(float y, float inv_p) {
    return ex2f(lg2f(y) * inv_p);
}

__global__ __launch_bounds__(WPB * 32, 6)   // cap regs ~40 -> 6 blocks/SM (75% occ)
void boilerplate_loss_kernel(const float* __restrict__ y_pred,
                             const int*   __restrict__ y_attack,
                             float*       __restrict__ out,
                             int nrows)
{
    __shared__ unsigned int smask[WPB][32];   // 1000-bit attack mask (rare path only)

    const int warp = threadIdx.x >> 5;
    const int lane = threadIdx.x & 31;
    const int row  = blockIdx.x * WPB + warp;
    if (row >= nrows) return;

    // --- build attack bitmask + gather attack logits (lanes 0..9) ---
    smask[warp][lane] = 0u;
    __syncwarp();

    float xa = 0.0f;
    if (lane < NK) {
        int idx = y_attack[row * NK + lane];
        xa = __ldg(&y_pred[(size_t)row * NC + idx]);
        atomicOr(&smask[warp][idx >> 5], 1u << (idx & 31));
    }
    __syncwarp();

    // --- hot pass: sum(exp(x)) + UNCONDITIONAL max (no mask tests, no packing) ---
    const float4* rowp = reinterpret_cast<const float4*>(y_pred + (size_t)row * NC);
    float s0 = 0.f, s1 = 0.f, s2 = 0.f, s3 = 0.f;
    float mxa = -INFINITY;
    #pragma unroll
    for (int j = 0; j < 8; j++) {
        int i = lane + 32 * j;
        if (j < 7 || i < NF4) {
            float4 v = rowp[i];
            s0 += ex2f(v.x * L2E);          // FMUL-imm + MUFU, no MOVs
            s1 += ex2f(v.y * L2E);
            s2 += ex2f(v.z * L2E);
            s3 += ex2f(v.w * L2E);
            mxa = fmaxf(mxa, fmaxf(fmaxf(v.x, v.y), fmaxf(v.z, v.w)));
        }
    }
    float s = (s0 + s1) + (s2 + s3);
    #pragma unroll
    for (int o = 16; o > 0; o >>= 1) {
        s += __shfl_xor_sync(0xffffffffu, s, o);
        mxa = fmaxf(mxa, __shfl_xor_sync(0xffffffffu, mxa, o));
    }

    // --- max over attack logits; detect the rare argmax-is-attacked case ---
    float mxatt = (lane < NK) ? xa : -INFINITY;
    #pragma unroll
    for (int o = 16; o > 0; o >>= 1)
        mxatt = fmaxf(mxatt, __shfl_xor_sync(0xffffffffu, mxatt, o));

    float mx_non;
    if (mxa == mxatt) {
        // rare (~1% of rows), warp-uniform: masked rescan (row is L2-hot).
        // unroll 2: keep register pressure low, this path is off the clock.
        float m = -INFINITY;
        #pragma unroll 2
        for (int j = 0; j < 8; j++) {
            int i = lane + 32 * j;
            if (i < NF4) {
                float4 v = rowp[i];
                unsigned int bits = (smask[warp][i >> 3] >> ((i & 7) * 4)) & 0xFu;
                if (!(bits & 1u)) m = fmaxf(m, v.x);
                if (!(bits & 2u)) m = fmaxf(m, v.y);
                if (!(bits & 4u)) m = fmaxf(m, v.z);
                if (!(bits & 8u)) m = fmaxf(m, v.w);
            }
        }
        #pragma unroll
        for (int o = 16; o > 0; o >>= 1)
            m = fmaxf(m, __shfl_xor_sync(0xffffffffu, m, o));
        mx_non = m;
    } else {
        mx_non = mxa;
    }

    // --- attack probs, min, macro loss ---
    float inv_s = __frcp_rn(s);
    float p = (lane < NK) ? (ex2f(xa * L2E) * inv_s) : INFINITY;
    float pmin = p;
    #pragma unroll
    for (int o = 16; o > 0; o >>= 1)
        pmin = fminf(pmin, __shfl_xor_sync(0xffffffffu, pmin, o));
    float pmax_non = ex2f(mx_non * L2E) * inv_s;
    float macro = pmax_non - pmin;

    // --- sorting term: diffs of consecutive attack probs, gen-mean p=9 ---
    float pnext = __shfl_down_sync(0xffffffffu, p, 1);
    float term = 0.0f;
    if (lane < NK - 1) {
        float d  = pnext - p;                  // in [-1, 1]
        float sv = 5.0f + 5.0f * d;            // surject to [0, 10]
        term = pow9f(sv);
    }
    #pragma unroll
    for (int o = 16; o > 0; o >>= 1)
        term += __shfl_xor_sync(0xffffffffu, term, o);

    if (lane == 0) {
        float gm9 = rootf(term * (1.0f / 9.0f), 1.0f / 9.0f);
        float sorting = (gm9 - 5.0f) * 0.2f;
        float c0 = 5.0f + 5.0f * macro;
        float c1 = 5.0f + 5.0f * sorting;
        float m = (pow10f(c0) + pow10f(c1)) * 0.5f;
        float fin = rootf(m, 0.1f);
        out[row] = (fin - 5.0f) * 0.2f;
    }
}

extern "C" void kernel_launch(void* const* d_in, const int* in_sizes, int n_in,
                              void* d_out, int out_size)
{
    const float* y_pred   = (const float*)d_in[0];
    const int*   y_attack = (const int*)d_in[1];
    float*       out      = (float*)d_out;
    int nrows = in_sizes[1] / NK;   // 32768

    int blocks = (nrows + WPB - 1) / WPB;
    boilerplate_loss_kernel<<<blocks, WPB * 32>>>(y_pred, y_attack, out, nrows);
}

// round 10
// speedup vs baseline: 1.0083x; 1.0083x over previous
#include <cuda_runtime.h>
#include <math.h>

#define WPB 8           // warps per block
#define NC  1000        // classes
#define NF4 250         // float4 per row
#define NK  10          // attack classes per row
#define L2E 1.4426950408889634f

__device__ __forceinline__ float ex2f(float x) {
    float r; asm("ex2.approx.f32 %0, %1;" : "=f"(r) : "f"(x)); return r;
}
__device__ __forceinline__ float lg2f(float x) {
    float r; asm("lg2.approx.f32 %0, %1;" : "=f"(r) : "f"(x)); return r;
}
// L2 evict_last policy: pins y_pred in the ~126MB L2 across graph replays
__device__ __forceinline__ unsigned long long mk_policy() {
    unsigned long long pol;
    asm("createpolicy.fractional.L2::evict_last.b64 %0, 1.0;" : "=l"(pol));
    return pol;
}
__device__ __forceinline__ float4 ldg_el(const float4* p, unsigned long long pol) {
    float4 v;
    asm("ld.global.nc.L2::cache_hint.v4.f32 {%0,%1,%2,%3}, [%4], %5;"
        : "=f"(v.x), "=f"(v.y), "=f"(v.z), "=f"(v.w) : "l"(p), "l"(pol));
    return v;
}
__device__ __forceinline__ float ldg_el_f(const float* p, unsigned long long pol) {
    float v;
    asm("ld.global.nc.L2::cache_hint.f32 %0, [%1], %2;" : "=f"(v) : "l"(p), "l"(pol));
    return v;
}
__device__ __forceinline__ float pow9f(float x) {
    float x2 = x * x, x4 = x2 * x2, x8 = x4 * x4; return x8 * x;
}
__device__ __forceinline__ float pow10f(float x) {
    float x2 = x * x, x4 = x2 * x2, x8 = x4 * x4; return x8 * x2;
}
__device__ __forceinline__ float rootf(float y, float inv_p) {
    return ex2f(lg2f(y) * inv_p);
}

__global__ __launch_bounds__(WPB * 32, 6)
void boilerplate_loss_kernel(const float* __restrict__ y_pred,
                             const int*   __restrict__ y_attack,
                             float*       __restrict__ out,
                             int nrows)
{
    __shared__ unsigned int smask[WPB][32];   // 1000-bit attack mask (rare path only)

    const int warp = threadIdx.x >> 5;
    const int lane = threadIdx.x & 31;
    const int row  = blockIdx.x * WPB + warp;
    if (row >= nrows) return;

    const unsigned long long pol = mk_policy();

    // --- build attack bitmask + gather attack logits (lanes 0..9) ---
    smask[warp][lane] = 0u;
    __syncwarp();

    float xa = 0.0f;
    if (lane < NK) {
        int idx = y_attack[row * NK + lane];
        xa = ldg_el_f(&y_pred[(size_t)row * NC + idx], pol);
        atomicOr(&smask[warp][idx >> 5], 1u << (idx & 31));
    }
    __syncwarp();

    // --- hot pass: sum(exp(x)) + unconditional max ---
    const float4* rowp = reinterpret_cast<const float4*>(y_pred + (size_t)row * NC);
    float s0 = 0.f, s1 = 0.f, s2 = 0.f, s3 = 0.f;
    float mxa = -INFINITY;
    #pragma unroll
    for (int j = 0; j < 8; j++) {
        int i = lane + 32 * j;
        if (j < 7 || i < NF4) {
            float4 v = ldg_el(rowp + i, pol);
            s0 += ex2f(v.x * L2E);
            s1 += ex2f(v.y * L2E);
            s2 += ex2f(v.z * L2E);
            s3 += ex2f(v.w * L2E);
            mxa = fmaxf(mxa, fmaxf(fmaxf(v.x, v.y), fmaxf(v.z, v.w)));
        }
    }
    float s = (s0 + s1) + (s2 + s3);
    #pragma unroll
    for (int o = 16; o > 0; o >>= 1) {
        s += __shfl_xor_sync(0xffffffffu, s, o);
        mxa = fmaxf(mxa, __shfl_xor_sync(0xffffffffu, mxa, o));
    }

    // --- max over attack logits; detect the rare argmax-is-attacked case ---
    float mxatt = (lane < NK) ? xa : -INFINITY;
    #pragma unroll
    for (int o = 16; o > 0; o >>= 1)
        mxatt = fmaxf(mxatt, __shfl_xor_sync(0xffffffffu, mxatt, o));

    float mx_non;
    if (mxa == mxatt) {
        // rare (~1% of rows), warp-uniform: masked rescan (row is cache-hot)
        float m = -INFINITY;
        #pragma unroll 2
        for (int j = 0; j < 8; j++) {
            int i = lane + 32 * j;
            if (i < NF4) {
                float4 v = ldg_el(rowp + i, pol);
                unsigned int bits = (smask[warp][i >> 3] >> ((i & 7) * 4)) & 0xFu;
                if (!(bits & 1u)) m = fmaxf(m, v.x);
                if (!(bits & 2u)) m = fmaxf(m, v.y);
                if (!(bits & 4u)) m = fmaxf(m, v.z);
                if (!(bits & 8u)) m = fmaxf(m, v.w);
            }
        }
        #pragma unroll
        for (int o = 16; o > 0; o >>= 1)
            m = fmaxf(m, __shfl_xor_sync(0xffffffffu, m, o));
        mx_non = m;
    } else {
        mx_non = mxa;
    }

    // --- attack probs, min, macro loss ---
    float inv_s = __frcp_rn(s);
    float p = (lane < NK) ? (ex2f(xa * L2E) * inv_s) : INFINITY;
    float pmin = p;
    #pragma unroll
    for (int o = 16; o > 0; o >>= 1)
        pmin = fminf(pmin, __shfl_xor_sync(0xffffffffu, pmin, o));
    float pmax_non = ex2f(mx_non * L2E) * inv_s;
    float macro = pmax_non - pmin;

    // --- sorting term: diffs of consecutive attack probs, gen-mean p=9 ---
    float pnext = __shfl_down_sync(0xffffffffu, p, 1);
    float term = 0.0f;
    if (lane < NK - 1) {
        float d  = pnext - p;                  // in [-1, 1]
        float sv = 5.0f + 5.0f * d;            // surject to [0, 10]
        term = pow9f(sv);
    }
    #pragma unroll
    for (int o = 16; o > 0; o >>= 1)
        term += __shfl_xor_sync(0xffffffffu, term, o);

    if (lane == 0) {
        float gm9 = rootf(term * (1.0f / 9.0f), 1.0f / 9.0f);
        float sorting = (gm9 - 5.0f) * 0.2f;
        float c0 = 5.0f + 5.0f * macro;
        float c1 = 5.0f + 5.0f * sorting;
        float m = (pow10f(c0) + pow10f(c1)) * 0.5f;
        float fin = rootf(m, 0.1f);
        out[row] = (fin - 5.0f) * 0.2f;
    }
}

extern "C" void kernel_launch(void* const* d_in, const int* in_sizes, int n_in,
                              void* d_out, int out_size)
{
    const float* y_pred   = (const float*)d_in[0];
    const int*   y_attack = (const int*)d_in[1];
    float*       out      = (float*)d_out;
    int nrows = in_sizes[1] / NK;   // 32768

    int blocks = (nrows + WPB - 1) / WPB;
    boilerplate_loss_kernel<<<blocks, WPB * 32>>>(y_pred, y_attack, out, nrows);
}

// round 11
// speedup vs baseline: 1.0188x; 1.0104x over previous
#include <cuda_runtime.h>
#include <math.h>

#define WPB  8          // warps per block
#define NC   1000       // classes
#define NF4  250        // float4 per row
#define NK   10         // attack classes per row
#define L2E  1.4426950408889634f
#define NBLK 740        // 148 SMs x 5 blocks/SM, persistent

__device__ __forceinline__ float ex2f(float x) {
    float r; asm("ex2.approx.f32 %0, %1;" : "=f"(r) : "f"(x)); return r;
}
__device__ __forceinline__ float lg2f(float x) {
    float r; asm("lg2.approx.f32 %0, %1;" : "=f"(r) : "f"(x)); return r;
}
__device__ __forceinline__ float pow9f(float x) {
    float x2 = x * x, x4 = x2 * x2, x8 = x4 * x4; return x8 * x;
}
__device__ __forceinline__ float pow10f(float x) {
    float x2 = x * x, x4 = x2 * x2, x8 = x4 * x4; return x8 * x2;
}
__device__ __forceinline__ float rootf(float y, float inv_p) {
    return ex2f(lg2f(y) * inv_p);
}

__global__ __launch_bounds__(WPB * 32, 5)
void boilerplate_loss_kernel(const float* __restrict__ y_pred,
                             const int*   __restrict__ y_attack,
                             float*       __restrict__ out,
                             int nrows)
{
    __shared__ unsigned int smask[WPB][32];   // only touched on the rare path

    const int warp   = threadIdx.x >> 5;
    const int lane   = threadIdx.x & 31;
    const int gwarp  = blockIdx.x * WPB + warp;
    const int nwarps = gridDim.x * WPB;

    for (int row = gwarp; row < nrows; row += nwarps) {
        const float4* rowp = reinterpret_cast<const float4*>(y_pred + (size_t)row * NC);

        // --- 1) batch ALL row loads up front (MLP = 8), sentinel for tail ---
        float4 v[8];
        #pragma unroll
        for (int j = 0; j < 8; j++) {
            int i = lane + 32 * j;
            if (j < 7 || i < NF4) v[j] = __ldg(rowp + i);
            else                  v[j] = make_float4(-INFINITY, -INFINITY, -INFINITY, -INFINITY);
        }

        // --- 2) sum(exp) + unconditional max (ex2(-inf)=0, fmax no-op on sentinel) ---
        float s0 = 0.f, s1 = 0.f, s2 = 0.f, s3 = 0.f;
        float mxa = -INFINITY;
        #pragma unroll
        for (int j = 0; j < 8; j++) {
            s0 += ex2f(v[j].x * L2E);
            s1 += ex2f(v[j].y * L2E);
            s2 += ex2f(v[j].z * L2E);
            s3 += ex2f(v[j].w * L2E);
            mxa = fmaxf(mxa, fmaxf(fmaxf(v[j].x, v[j].y), fmaxf(v[j].z, v[j].w)));
        }
        float s = (s0 + s1) + (s2 + s3);
        #pragma unroll
        for (int o = 16; o > 0; o >>= 1) {
            s += __shfl_xor_sync(0xffffffffu, s, o);
            mxa = fmaxf(mxa, __shfl_xor_sync(0xffffffffu, mxa, o));
        }

        // --- 3) gather attack logits now (row lines are L1-hot) ---
        int   idx = 0;
        float xa  = 0.0f;
        if (lane < NK) {
            idx = y_attack[row * NK + lane];
            xa  = __ldg(&y_pred[(size_t)row * NC + idx]);
        }
        float mxatt = (lane < NK) ? xa : -INFINITY;
        #pragma unroll
        for (int o = 16; o > 0; o >>= 1)
            mxatt = fmaxf(mxatt, __shfl_xor_sync(0xffffffffu, mxatt, o));

        // --- 4) non-attack max; rare warp-uniform path rescans from registers ---
        float mx_non;
        if (mxa == mxatt) {
            smask[warp][lane] = 0u;
            __syncwarp();
            if (lane < NK) atomicOr(&smask[warp][idx >> 5], 1u << (idx & 31));
            __syncwarp();
            float m = -INFINITY;
            #pragma unroll
            for (int j = 0; j < 8; j++) {
                int i = lane + 32 * j;
                unsigned int bits = (smask[warp][i >> 3] >> ((i & 7) * 4)) & 0xFu;
                if (!(bits & 1u)) m = fmaxf(m, v[j].x);   // sentinel lanes are -inf: harmless
                if (!(bits & 2u)) m = fmaxf(m, v[j].y);
                if (!(bits & 4u)) m = fmaxf(m, v[j].z);
                if (!(bits & 8u)) m = fmaxf(m, v[j].w);
            }
            #pragma unroll
            for (int o = 16; o > 0; o >>= 1)
                m = fmaxf(m, __shfl_xor_sync(0xffffffffu, m, o));
            mx_non = m;
            __syncwarp();
        } else {
            mx_non = mxa;
        }

        // --- 5) attack probs, min, macro loss ---
        float inv_s = __frcp_rn(s);
        float p = (lane < NK) ? (ex2f(xa * L2E) * inv_s) : INFINITY;
        float pmin = p;
        #pragma unroll
        for (int o = 16; o > 0; o >>= 1)
            pmin = fminf(pmin, __shfl_xor_sync(0xffffffffu, pmin, o));
        float pmax_non = ex2f(mx_non * L2E) * inv_s;
        float macro = pmax_non - pmin;

        // --- 6) sorting term: diffs of consecutive attack probs, gen-mean p=9 ---
        float pnext = __shfl_down_sync(0xffffffffu, p, 1);
        float term = 0.0f;
        if (lane < NK - 1) {
            float d  = pnext - p;              // in [-1, 1]
            float sv = 5.0f + 5.0f * d;        // surject to [0, 10]
            term = pow9f(sv);
        }
        #pragma unroll
        for (int o = 16; o > 0; o >>= 1)
            term += __shfl_xor_sync(0xffffffffu, term, o);

        if (lane == 0) {
            float gm9 = rootf(term * (1.0f / 9.0f), 1.0f / 9.0f);
            float sorting = (gm9 - 5.0f) * 0.2f;
            float c0 = 5.0f + 5.0f * macro;
            float c1 = 5.0f + 5.0f * sorting;
            float m = (pow10f(c0) + pow10f(c1)) * 0.5f;
            float fin = rootf(m, 0.1f);
            out[row] = (fin - 5.0f) * 0.2f;
        }
    }
}

extern "C" void kernel_launch(void* const* d_in, const int* in_sizes, int n_in,
                              void* d_out, int out_size)
{
    const float* y_pred   = (const float*)d_in[0];
    const int*   y_attack = (const int*)d_in[1];
    float*       out      = (float*)d_out;
    int nrows = in_sizes[1] / NK;   // 32768

    int blocks = NBLK;
    if (blocks * WPB > nrows) blocks = (nrows + WPB - 1) / WPB;
    boilerplate_loss_kernel<<<blocks, WPB * 32>>>(y_pred, y_attack, out, nrows);
}

// round 12
// speedup vs baseline: 1.0725x; 1.0527x over previous
#include <cuda_runtime.h>
#include <math.h>

#define WPB  8          // warps per block
#define NC   1000       // classes
#define NF8  125        // 32B-chunks (8 floats) per row
#define NK   10         // attack classes per row
#define L2E  1.4426950408889634f
#define NBLK 740        // 148 SMs x 5 blocks/SM, persistent

__device__ __forceinline__ float ex2f(float x) {
    float r; asm("ex2.approx.f32 %0, %1;" : "=f"(r) : "f"(x)); return r;
}
__device__ __forceinline__ float lg2f(float x) {
    float r; asm("lg2.approx.f32 %0, %1;" : "=f"(r) : "f"(x)); return r;
}
__device__ __forceinline__ float pow9f(float x) {
    float x2 = x * x, x4 = x2 * x2, x8 = x4 * x4; return x8 * x;
}
__device__ __forceinline__ float pow10f(float x) {
    float x2 = x * x, x4 = x2 * x2, x8 = x4 * x4; return x8 * x2;
}
__device__ __forceinline__ float rootf(float y, float inv_p) {
    return ex2f(lg2f(y) * inv_p);
}

struct F8 { float a[8]; };

// 256-bit load: one LDG slot carries 1KB/warp instead of 512B
__device__ __forceinline__ F8 ldg256(const float* p) {
    F8 v;
    unsigned r0,r1,r2,r3,r4,r5,r6,r7;
    asm("ld.global.nc.v8.b32 {%0,%1,%2,%3,%4,%5,%6,%7}, [%8];"
        : "=r"(r0),"=r"(r1),"=r"(r2),"=r"(r3),
          "=r"(r4),"=r"(r5),"=r"(r6),"=r"(r7) : "l"(p));
    v.a[0]=__int_as_float(r0); v.a[1]=__int_as_float(r1);
    v.a[2]=__int_as_float(r2); v.a[3]=__int_as_float(r3);
    v.a[4]=__int_as_float(r4); v.a[5]=__int_as_float(r5);
    v.a[6]=__int_as_float(r6); v.a[7]=__int_as_float(r7);
    return v;
}

__global__ __launch_bounds__(WPB * 32, 5)
void boilerplate_loss_kernel(const float* __restrict__ y_pred,
                             const int*   __restrict__ y_attack,
                             float*       __restrict__ out,
                             int nrows)
{
    __shared__ unsigned int smask[WPB][32];   // only touched on the rare path

    const int warp   = threadIdx.x >> 5;
    const int lane   = threadIdx.x & 31;
    const int gwarp  = blockIdx.x * WPB + warp;
    const int nwarps = gridDim.x * WPB;

    for (int row = gwarp; row < nrows; row += nwarps) {
        const float* rowbase = y_pred + (size_t)row * NC;

        // --- 1) batch the whole row as 4 x LDG.256 per lane (2x bytes/slot) ---
        F8 v[4];
        #pragma unroll
        for (int j = 0; j < 4; j++) {
            int i = lane + 32 * j;            // 32-byte chunk index, 0..127
            if (j < 3 || i < NF8) {
                v[j] = ldg256(rowbase + i * 8);
            } else {
                #pragma unroll
                for (int k = 0; k < 8; k++) v[j].a[k] = -INFINITY;
            }
        }

        // --- 2) sum(exp) + unconditional max (ex2(-inf)=0, fmax no-op) ---
        float s0 = 0.f, s1 = 0.f, s2 = 0.f, s3 = 0.f;
        float mxa = -INFINITY;
        #pragma unroll
        for (int j = 0; j < 4; j++) {
            s0 += ex2f(v[j].a[0] * L2E) + ex2f(v[j].a[4] * L2E);
            s1 += ex2f(v[j].a[1] * L2E) + ex2f(v[j].a[5] * L2E);
            s2 += ex2f(v[j].a[2] * L2E) + ex2f(v[j].a[6] * L2E);
            s3 += ex2f(v[j].a[3] * L2E) + ex2f(v[j].a[7] * L2E);
            float m01 = fmaxf(fmaxf(v[j].a[0], v[j].a[1]), fmaxf(v[j].a[2], v[j].a[3]));
            float m23 = fmaxf(fmaxf(v[j].a[4], v[j].a[5]), fmaxf(v[j].a[6], v[j].a[7]));
            mxa = fmaxf(mxa, fmaxf(m01, m23));
        }
        float s = (s0 + s1) + (s2 + s3);
        #pragma unroll
        for (int o = 16; o > 0; o >>= 1) {
            s += __shfl_xor_sync(0xffffffffu, s, o);
            mxa = fmaxf(mxa, __shfl_xor_sync(0xffffffffu, mxa, o));
        }

        // --- 3) gather attack logits (row lines are L1-hot now) ---
        int   idx = 0;
        float xa  = 0.0f;
        if (lane < NK) {
            idx = y_attack[row * NK + lane];
            xa  = __ldg(&rowbase[idx]);
        }
        float mxatt = (lane < NK) ? xa : -INFINITY;
        #pragma unroll
        for (int o = 16; o > 0; o >>= 1)
            mxatt = fmaxf(mxatt, __shfl_xor_sync(0xffffffffu, mxatt, o));

        // --- 4) non-attack max; rare warp-uniform path rescans from registers ---
        float mx_non;
        if (mxa == mxatt) {
            smask[warp][lane] = 0u;
            __syncwarp();
            if (lane < NK) atomicOr(&smask[warp][idx >> 5], 1u << (idx & 31));
            __syncwarp();
            float m = -INFINITY;
            #pragma unroll
            for (int j = 0; j < 4; j++) {
                int i = lane + 32 * j;                      // chunk of classes 8i..8i+7
                unsigned int bits = (smask[warp][i >> 2] >> ((i & 3) * 8)) & 0xFFu;
                #pragma unroll
                for (int k = 0; k < 8; k++)
                    if (!(bits & (1u << k))) m = fmaxf(m, v[j].a[k]);
            }
            #pragma unroll
            for (int o = 16; o > 0; o >>= 1)
                m = fmaxf(m, __shfl_xor_sync(0xffffffffu, m, o));
            mx_non = m;
            __syncwarp();
        } else {
            mx_non = mxa;
        }

        // --- 5) attack probs, min, macro loss ---
        float inv_s = __frcp_rn(s);
        float p = (lane < NK) ? (ex2f(xa * L2E) * inv_s) : INFINITY;
        float pmin = p;
        #pragma unroll
        for (int o = 16; o > 0; o >>= 1)
            pmin = fminf(pmin, __shfl_xor_sync(0xffffffffu, pmin, o));
        float pmax_non = ex2f(mx_non * L2E) * inv_s;
        float macro = pmax_non - pmin;

        // --- 6) sorting term: diffs of consecutive attack probs, gen-mean p=9 ---
        float pnext = __shfl_down_sync(0xffffffffu, p, 1);
        float term = 0.0f;
        if (lane < NK - 1) {
            float d  = pnext - p;              // in [-1, 1]
            float sv = 5.0f + 5.0f * d;        // surject to [0, 10]
            term = pow9f(sv);
        }
        #pragma unroll
        for (int o = 16; o > 0; o >>= 1)
            term += __shfl_xor_sync(0xffffffffu, term, o);

        if (lane == 0) {
            float gm9 = rootf(term * (1.0f / 9.0f), 1.0f / 9.0f);
            float sorting = (gm9 - 5.0f) * 0.2f;
            float c0 = 5.0f + 5.0f * macro;
            float c1 = 5.0f + 5.0f * sorting;
            float m = (pow10f(c0) + pow10f(c1)) * 0.5f;
            float fin = rootf(m, 0.1f);
            out[row] = (fin - 5.0f) * 0.2f;
        }
    }
}

extern "C" void kernel_launch(void* const* d_in, const int* in_sizes, int n_in,
                              void* d_out, int out_size)
{
    const float* y_pred   = (const float*)d_in[0];
    const int*   y_attack = (const int*)d_in[1];
    float*       out      = (float*)d_out;
    int nrows = in_sizes[1] / NK;   // 32768

    int blocks = NBLK;
    if (blocks * WPB > nrows) blocks = (nrows + WPB - 1) / WPB;
    boilerplate_loss_kernel<<<blocks, WPB * 32>>>(y_pred, y_attack, out, nrows);
}